// round 11
// baseline (speedup 1.0000x reference)
#include <cuda_runtime.h>

#define BB 64
#define TT 512
#define II 512
#define HH 1024

// Recurrence tiling: 128 CTAs = 4 row-groups (16 rows) x 32 col-groups (32 cols).
#define RG_ROWS 16
#define CG_COLS 32

// h double buffer (ring) + per-CTA publish flags — static device globals.
__device__ float g_h[2][BB * HH];
__device__ int g_flag[128];

// ---------------------------------------------------------------------------
// Packed f32x2 helpers (Blackwell FFMA2 — ptxas never auto-fuses; PTX only).
// ---------------------------------------------------------------------------
__device__ __forceinline__ unsigned long long pack2(float v) {
    unsigned long long r;
    asm("mov.b64 %0, {%1, %1};" : "=l"(r) : "f"(v));
    return r;
}
__device__ __forceinline__ void fma2(unsigned long long& d,
                                     unsigned long long a,
                                     unsigned long long b) {
    asm("fma.rn.f32x2 %0, %1, %2, %0;" : "+l"(d) : "l"(a), "l"(b));
}
__device__ __forceinline__ void add2(unsigned long long& d,
                                     unsigned long long a) {
    asm("add.rn.f32x2 %0, %0, %1;" : "+l"(d) : "l"(a));
}
__device__ __forceinline__ void unpack2(unsigned long long v, float& lo, float& hi) {
    asm("mov.b64 {%0, %1}, %2;" : "=f"(lo), "=f"(hi) : "l"(v));
}
__device__ __forceinline__ unsigned long long dl(double d) {
    return __double_as_longlong(d);
}

// Acquire-spin until *p >= want. Whole warp polls the same address (broadcast).
__device__ __forceinline__ void wait_flag(const int* p, int want) {
    int v;
    do {
        asm volatile("ld.acquire.gpu.global.b32 %0, [%1];"
                     : "=r"(v) : "l"(p) : "memory");
    } while (v < want);
}

// ---------------------------------------------------------------------------
// Phase 1: x_proj = inputs(32768x512) @ W_xh(512x1024) + b  -> written to out.
// 128x128 tile, 8x8 microtile, BK=16, packed FFMA2 inner product.
// CTA (0,0) additionally resets the dataflow flags and stages h_prev into
// ring[0] (stream order guarantees visibility to rnn_recur).
// ---------------------------------------------------------------------------
__global__ __launch_bounds__(256, 2) void xproj_gemm(
    const float* __restrict__ A, const float* __restrict__ W,
    const float* __restrict__ bias, const float* __restrict__ h_prev,
    float* __restrict__ C) {
    __shared__ __align__(16) float As[16][128];   // As[k][m]
    __shared__ __align__(16) float Bs[16][128];   // Bs[k][n]

    const int tid = threadIdx.x;

    // Merged init (one CTA): flags = 0 (step 0 = h_prev published), ring[0].
    if (blockIdx.x == 0 && blockIdx.y == 0) {
        if (tid < 128) g_flag[tid] = 0;
        const float4* hp4 = (const float4*)h_prev;
        float4* r0 = (float4*)g_h[0];
#pragma unroll
        for (int i = 0; i < 64; i++)
            r0[tid + i * 256] = hp4[tid + i * 256];
    }

    const int m0 = blockIdx.y * 128;
    const int n0 = blockIdx.x * 128;
    const int tx = tid & 15;        // n microtile
    const int ty = tid >> 4;        // m microtile

    const int aRow = tid >> 2;
    const int aK   = (tid & 3) * 4;
    const int bRow = tid >> 5;
    const int bC   = (tid & 31) * 4;

    unsigned long long acc2[8][4];
#pragma unroll
    for (int i = 0; i < 8; i++)
#pragma unroll
        for (int j = 0; j < 4; j++) acc2[i][j] = 0ull;

    for (int k0 = 0; k0 < II; k0 += 16) {
#pragma unroll
        for (int it = 0; it < 2; it++) {
            int row = aRow + it * 64;
            float4 v = *(const float4*)&A[(size_t)(m0 + row) * II + k0 + aK];
            As[aK + 0][row] = v.x;
            As[aK + 1][row] = v.y;
            As[aK + 2][row] = v.z;
            As[aK + 3][row] = v.w;
        }
#pragma unroll
        for (int it = 0; it < 2; it++) {
            int rr = bRow + it * 8;
            *(float4*)&Bs[rr][bC] =
                *(const float4*)&W[(size_t)(k0 + rr) * HH + n0 + bC];
        }
        __syncthreads();
#pragma unroll
        for (int kk = 0; kk < 16; kk++) {
            float a[8];
            *(float4*)&a[0] = *(const float4*)&As[kk][ty * 8];
            *(float4*)&a[4] = *(const float4*)&As[kk][ty * 8 + 4];
            double2 bx = *(const double2*)&Bs[kk][tx * 8];
            double2 by = *(const double2*)&Bs[kk][tx * 8 + 4];
            unsigned long long b01 = dl(bx.x), b23 = dl(bx.y);
            unsigned long long b45 = dl(by.x), b67 = dl(by.y);
#pragma unroll
            for (int i = 0; i < 8; i++) {
                unsigned long long ap = pack2(a[i]);
                fma2(acc2[i][0], ap, b01);
                fma2(acc2[i][1], ap, b23);
                fma2(acc2[i][2], ap, b45);
                fma2(acc2[i][3], ap, b67);
            }
        }
        __syncthreads();
    }

#pragma unroll
    for (int i = 0; i < 8; i++) {
        int row = m0 + ty * 8 + i;
        float c[8];
#pragma unroll
        for (int j = 0; j < 4; j++) unpack2(acc2[i][j], c[2 * j], c[2 * j + 1]);
#pragma unroll
        for (int j = 0; j < 8; j++) c[j] += bias[n0 + tx * 8 + j];
        *(float4*)&C[(size_t)row * HH + n0 + tx * 8]     = *(float4*)&c[0];
        *(float4*)&C[(size_t)row * HH + n0 + tx * 8 + 4] = *(float4*)&c[4];
    }
}

// ---------------------------------------------------------------------------
// Phase 2: persistent recurrence, NO global barrier — producer/consumer
// chunk dataflow within each row group.
//
// CTA (rg, cgp): owns output tile rows rg*16..+16, cols cgp*32..+32.
// W tile (1024 x 32, 128 KB) lives in smem for all 512 steps.
// Per step t (t = 1..512, h_t from h_{t-1}):
//   Each warp (fixed rhi, kh) consumes its 16 k-chunks of 32: for chunk
//   p = kh*16+cc it acquire-spins on g_flag[rg*32+p] >= t-1, LDGs its 4 h
//   rows x 32 k into registers (double-buffered, overlapping FMAs of the
//   previous chunk), and accumulates against smem W via packed FFMA2.
//   Epilogue: split-k reduce (smem), tanh, write out + ring[t&1], then
//   __threadfence + st.release flag = t.
//
// Safety of the 2-deep ring: publishing step t requires having observed
// flag >= t-1 from ALL 32 rg-mates, i.e. everyone finished READING step
// t-2 — exactly the data that ring[t&1] overwrites. Flags reset per launch
// by the merged init in xproj_gemm. 128 CTAs, 1/SM (133 KB smem) — all
// co-resident, so spins always make progress.
// ---------------------------------------------------------------------------
__global__ __launch_bounds__(256, 1) void rnn_recur(
    const float* __restrict__ Whh, float* __restrict__ out) {
    extern __shared__ __align__(16) float smem_dyn[];
    float* ws = smem_dyn;                               // [1024][32]
    ulonglong2* red = (ulonglong2*)(ws + 1024 * CG_COLS);  // [128]

    const int tid = threadIdx.x;
    const int rlo = tid & 3;
    const int cg  = (tid >> 2) & 7;
    const int kh  = (tid >> 5) & 1;
    const int rhi = tid >> 6;
    const int r   = rhi * 4 + rlo;

    const int rg       = blockIdx.x >> 5;
    const int rowbase  = rg * RG_ROWS;
    const int colbase  = (blockIdx.x & 31) * CG_COLS;
    const int c        = colbase + cg * 4;
    const int flagbase = rg * 32;

    // --- Prologue: load W tile (1024 x 32) into smem, once. ---
    {
        const float4* wsrc0 = (const float4*)(Whh + colbase);
        float4* wdst = (float4*)ws;
#pragma unroll
        for (int i = 0; i < 32; i++) {
            int idx4 = tid + i * 256;           // 8192 float4 total
            int k  = idx4 >> 3;                 // 8 float4 per W row
            int c4 = idx4 & 7;
            wdst[idx4] = wsrc0[(size_t)k * (HH / 4) + c4];
        }
    }
    __syncthreads();

    const int cgp0 = kh * 16;                   // this warp's first chunk

    for (int t = 1; t <= TT; t++) {
        const float* ring_r = g_h[(t - 1) & 1] + (size_t)(rowbase + r) * HH;

        // Prefetch x_proj operand (independent of h flow).
        float4 xp;
        size_t oidx = 0;
        if (!kh) {
            oidx = ((size_t)(rowbase + r) * TT + (t - 1)) * HH + c;
            xp = *(const float4*)&out[oidx];
        }

        unsigned long long a01 = 0ull, a23 = 0ull;

        // h chunk double buffer: 2 x 32 floats in registers.
        float4 hb[2][8];
        wait_flag(&g_flag[flagbase + cgp0], t - 1);
        {
            const float4* src = (const float4*)(ring_r + cgp0 * 32);
#pragma unroll
            for (int i = 0; i < 8; i++) hb[0][i] = __ldcg(&src[i]);
        }

#pragma unroll 2
        for (int cc = 0; cc < 16; cc++) {
            const int cur = cc & 1;
            if (cc < 15) {
                wait_flag(&g_flag[flagbase + cgp0 + cc + 1], t - 1);
                const float4* src =
                    (const float4*)(ring_r + (cgp0 + cc + 1) * 32);
#pragma unroll
                for (int i = 0; i < 8; i++) hb[cur ^ 1][i] = __ldcg(&src[i]);
            }
            const float* wk = ws + (size_t)(cgp0 + cc) * 32 * CG_COLS + cg * 4;
            const float* hf = (const float*)hb[cur];
#pragma unroll
            for (int kl = 0; kl < 32; kl++) {
                double2 w = *(const double2*)(wk + (size_t)kl * CG_COLS);
                unsigned long long hp = pack2(hf[kl]);
                fma2(a01, hp, dl(w.x));
                fma2(a23, hp, dl(w.y));
            }
        }

        // --- Split-k reduce (2 halves) via smem. ---
        if (kh) red[r * 8 + cg] = make_ulonglong2(a01, a23);
        __syncthreads();

        if (!kh) {
            ulonglong2 p = red[r * 8 + cg];
            add2(a01, p.x);
            add2(a23, p.y);
            float s0, s1, s2, s3;
            unpack2(a01, s0, s1);
            unpack2(a23, s2, s3);
            float4 hv;
            hv.x = tanhf(s0 + xp.x);
            hv.y = tanhf(s1 + xp.y);
            hv.z = tanhf(s2 + xp.z);
            hv.w = tanhf(s3 + xp.w);
            *(float4*)&out[oidx] = hv;
            *(float4*)&g_h[t & 1][(size_t)(rowbase + r) * HH + c] = hv;
        }
        __syncthreads();

        // Publish: this CTA's step-t chunk is complete and visible.
        if (tid == 0) {
            __threadfence();
            asm volatile("st.release.gpu.global.b32 [%0], %1;"
                         :: "l"(&g_flag[blockIdx.x]), "r"(t) : "memory");
        }
    }
}

// ---------------------------------------------------------------------------
// inputs: d_in[0]=inputs (B,T,I) f32, d_in[1]=h_prev (B,H) f32,
//         d_in[2]=W_xh (I,H) f32, d_in[3]=W_hh (H,H) f32, d_in[4]=b_h (H) f32
// out: (B,T,H) f32
// ---------------------------------------------------------------------------
extern "C" void kernel_launch(void* const* d_in, const int* in_sizes, int n_in,
                              void* d_out, int out_size) {
    const float* x      = (const float*)d_in[0];
    const float* h_prev = (const float*)d_in[1];
    const float* W_xh   = (const float*)d_in[2];
    const float* W_hh   = (const float*)d_in[3];
    const float* b_h    = (const float*)d_in[4];
    float* out = (float*)d_out;

    (void)in_sizes; (void)n_in; (void)out_size;

    // 128 KB (W) + 2 KB (red) = 133120 B dynamic smem -> 1 CTA/SM.
    const int smem_bytes = 1024 * CG_COLS * 4 + 2048;
    cudaFuncSetAttribute(rnn_recur, cudaFuncAttributeMaxDynamicSharedMemorySize,
                         smem_bytes);

    xproj_gemm<<<dim3(HH / 128, (BB * TT) / 128), 256>>>(x, W_xh, b_h, h_prev, out);
    rnn_recur<<<128, 256, smem_bytes>>>(W_hh, out);
}

// round 12
// speedup vs baseline: 1.6392x; 1.6392x over previous
#include <cuda_runtime.h>

#define BB 64
#define TT 512
#define II 512
#define HH 1024

// Recurrence tiling: 128 CTAs = 4 row-groups (16 rows) x 32 col-groups (32 cols).
#define RG_ROWS 16
#define CG_COLS 32

// h double buffer (ring) + per-row-group monotone barrier counters.
// Counters are 256 B apart (64 ints): distinct L2 lines, no bit-7 pairing.
__device__ float g_h[2][BB * HH];
__device__ unsigned g_cnt[4 * 64];

// ---------------------------------------------------------------------------
// Packed f32x2 helpers (Blackwell FFMA2 — ptxas never auto-fuses; PTX only).
// ---------------------------------------------------------------------------
__device__ __forceinline__ unsigned long long pack2(float v) {
    unsigned long long r;
    asm("mov.b64 %0, {%1, %1};" : "=l"(r) : "f"(v));
    return r;
}
__device__ __forceinline__ void fma2(unsigned long long& d,
                                     unsigned long long a,
                                     unsigned long long b) {
    asm("fma.rn.f32x2 %0, %1, %2, %0;" : "+l"(d) : "l"(a), "l"(b));
}
__device__ __forceinline__ void add2(unsigned long long& d,
                                     unsigned long long a) {
    asm("add.rn.f32x2 %0, %0, %1;" : "+l"(d) : "l"(a));
}
__device__ __forceinline__ void unpack2(unsigned long long v, float& lo, float& hi) {
    asm("mov.b64 {%0, %1}, %2;" : "=f"(lo), "=f"(hi) : "l"(v));
}
__device__ __forceinline__ unsigned long long dl(double d) {
    return __double_as_longlong(d);
}

// ---------------------------------------------------------------------------
// Phase 1: x_proj = inputs(32768x512) @ W_xh(512x1024) + b  -> written to out.
// 128x128 tile, 8x8 microtile, BK=16, packed FFMA2 inner product.
// CTA (0,0) additionally resets the rg barrier counters and stages h_prev
// into ring[0] (stream order guarantees visibility to rnn_recur).
// ---------------------------------------------------------------------------
__global__ __launch_bounds__(256, 2) void xproj_gemm(
    const float* __restrict__ A, const float* __restrict__ W,
    const float* __restrict__ bias, const float* __restrict__ h_prev,
    float* __restrict__ C) {
    __shared__ __align__(16) float As[16][128];   // As[k][m]
    __shared__ __align__(16) float Bs[16][128];   // Bs[k][n]

    const int tid = threadIdx.x;

    // Merged init (one CTA): counters = 0, ring[0] = h_prev.
    if (blockIdx.x == 0 && blockIdx.y == 0) {
        if (tid < 4) g_cnt[tid * 64] = 0u;
        const float4* hp4 = (const float4*)h_prev;
        float4* r0 = (float4*)g_h[0];
#pragma unroll
        for (int i = 0; i < 64; i++)
            r0[tid + i * 256] = hp4[tid + i * 256];
    }

    const int m0 = blockIdx.y * 128;
    const int n0 = blockIdx.x * 128;
    const int tx = tid & 15;        // n microtile
    const int ty = tid >> 4;        // m microtile

    const int aRow = tid >> 2;
    const int aK   = (tid & 3) * 4;
    const int bRow = tid >> 5;
    const int bC   = (tid & 31) * 4;

    unsigned long long acc2[8][4];
#pragma unroll
    for (int i = 0; i < 8; i++)
#pragma unroll
        for (int j = 0; j < 4; j++) acc2[i][j] = 0ull;

    for (int k0 = 0; k0 < II; k0 += 16) {
#pragma unroll
        for (int it = 0; it < 2; it++) {
            int row = aRow + it * 64;
            float4 v = *(const float4*)&A[(size_t)(m0 + row) * II + k0 + aK];
            As[aK + 0][row] = v.x;
            As[aK + 1][row] = v.y;
            As[aK + 2][row] = v.z;
            As[aK + 3][row] = v.w;
        }
#pragma unroll
        for (int it = 0; it < 2; it++) {
            int rr = bRow + it * 8;
            *(float4*)&Bs[rr][bC] =
                *(const float4*)&W[(size_t)(k0 + rr) * HH + n0 + bC];
        }
        __syncthreads();
#pragma unroll
        for (int kk = 0; kk < 16; kk++) {
            float a[8];
            *(float4*)&a[0] = *(const float4*)&As[kk][ty * 8];
            *(float4*)&a[4] = *(const float4*)&As[kk][ty * 8 + 4];
            double2 bx = *(const double2*)&Bs[kk][tx * 8];
            double2 by = *(const double2*)&Bs[kk][tx * 8 + 4];
            unsigned long long b01 = dl(bx.x), b23 = dl(bx.y);
            unsigned long long b45 = dl(by.x), b67 = dl(by.y);
#pragma unroll
            for (int i = 0; i < 8; i++) {
                unsigned long long ap = pack2(a[i]);
                fma2(acc2[i][0], ap, b01);
                fma2(acc2[i][1], ap, b23);
                fma2(acc2[i][2], ap, b45);
                fma2(acc2[i][3], ap, b67);
            }
        }
        __syncthreads();
    }

#pragma unroll
    for (int i = 0; i < 8; i++) {
        int row = m0 + ty * 8 + i;
        float c[8];
#pragma unroll
        for (int j = 0; j < 4; j++) unpack2(acc2[i][j], c[2 * j], c[2 * j + 1]);
#pragma unroll
        for (int j = 0; j < 8; j++) c[j] += bias[n0 + tx * 8 + j];
        *(float4*)&C[(size_t)row * HH + n0 + tx * 8]     = *(float4*)&c[0];
        *(float4*)&C[(size_t)row * HH + n0 + tx * 8 + 4] = *(float4*)&c[4];
    }
}

// ---------------------------------------------------------------------------
// Phase 2: persistent recurrence. Sync = ONE per-row-group barrier per step
// (monotone counter, 32 arrivals); h streamed from L2 in register chunks.
//
// CTA (rg, cgp): rows rg*16..+16, cols cgp*32..+32. W tile (1024x32, 128 KB)
// smem-resident for all 512 steps. Threads: tid = rhi*64 + kh*32 + cg*4 + rlo,
// r = rhi*4+rlo (16 rows), cg (8 groups of 4 cols), kh (split-k half).
//
// Step t (h_t from h_{t-1}):
//   thread0 spins until g_cnt[rg] >= 32*(t-1) (acquire), __syncthreads.
//   Each thread streams h row r, k-half kh (512 floats) from ring[(t-1)&1]
//   via __ldcg in 8-float4 chunks, double-buffered against FFMA2 work on
//   smem-resident W. Split-k reduce in smem; !kh half does tanh and writes
//   out + ring[t&1]. Then __syncthreads, thread0: fence + red.release add 1.
//
// Ring safety (per rg): arriving at barrier t-1 means every rg CTA finished
// READING ring[(t-2)&1] = ring[t&1] — exactly what step t overwrites.
// Counters reset per launch by xproj_gemm. 128 CTAs, 1/SM — co-resident.
// ---------------------------------------------------------------------------
__global__ __launch_bounds__(256, 1) void rnn_recur(
    const float* __restrict__ Whh, float* __restrict__ out) {
    extern __shared__ __align__(16) float smem_dyn[];
    float* ws = smem_dyn;                               // [1024][32]
    ulonglong2* red = (ulonglong2*)(ws + 1024 * CG_COLS);  // [128]

    const int tid = threadIdx.x;
    const int rlo = tid & 3;
    const int cg  = (tid >> 2) & 7;
    const int kh  = (tid >> 5) & 1;
    const int rhi = tid >> 6;
    const int r   = rhi * 4 + rlo;

    const int rg      = blockIdx.x >> 5;
    const int rowbase = rg * RG_ROWS;
    const int colbase = (blockIdx.x & 31) * CG_COLS;
    const int c       = colbase + cg * 4;
    unsigned* cnt     = &g_cnt[rg * 64];

    // --- Prologue: load W tile (1024 x 32) into smem, once. ---
    {
        const float4* wsrc0 = (const float4*)(Whh + colbase);
        float4* wdst = (float4*)ws;
#pragma unroll
        for (int i = 0; i < 32; i++) {
            int idx4 = tid + i * 256;           // 8192 float4 total
            int k  = idx4 >> 3;                 // 8 float4 per W row
            int c4 = idx4 & 7;
            wdst[idx4] = wsrc0[(size_t)k * (HH / 4) + c4];
        }
    }
    __syncthreads();

    const float* wpf = ws + (size_t)kh * 512 * CG_COLS + cg * 4;

    for (int t = 1; t <= TT; t++) {
        // --- Wait: all 32 rg producers have published step t-1. ---
        if (t > 1) {
            if (tid == 0) {
                const unsigned want = 32u * (unsigned)(t - 1);
                unsigned v;
                do {
                    asm volatile("ld.acquire.gpu.global.b32 %0, [%1];"
                                 : "=r"(v) : "l"(cnt) : "memory");
                } while (v < want);
            }
            __syncthreads();
        }

        const float* ring_r =
            g_h[(t - 1) & 1] + (size_t)(rowbase + r) * HH + kh * 512;

        // Prefetch x_proj operand (independent of h flow).
        float4 xp;
        size_t oidx = 0;
        if (!kh) {
            oidx = ((size_t)(rowbase + r) * TT + (t - 1)) * HH + c;
            xp = *(const float4*)&out[oidx];
        }

        unsigned long long a01 = 0ull, a23 = 0ull;

        // h register double buffer: 2 x 32 floats (chunks of 32 k).
        float4 hb[2][8];
        {
            const float4* src = (const float4*)ring_r;
#pragma unroll
            for (int i = 0; i < 8; i++) hb[0][i] = __ldcg(&src[i]);
        }

#pragma unroll 2
        for (int cc = 0; cc < 16; cc++) {
            const int cur = cc & 1;
            if (cc < 15) {
                const float4* src = (const float4*)(ring_r + (cc + 1) * 32);
#pragma unroll
                for (int i = 0; i < 8; i++) hb[cur ^ 1][i] = __ldcg(&src[i]);
            }
            const float* wk = wpf + (size_t)cc * 32 * CG_COLS;
            const float* hf = (const float*)hb[cur];
#pragma unroll
            for (int kl = 0; kl < 32; kl++) {
                double2 w = *(const double2*)(wk + (size_t)kl * CG_COLS);
                unsigned long long hp = pack2(hf[kl]);
                fma2(a01, hp, dl(w.x));
                fma2(a23, hp, dl(w.y));
            }
        }

        // --- Split-k reduce (2 halves) via smem. ---
        if (kh) red[r * 8 + cg] = make_ulonglong2(a01, a23);
        __syncthreads();

        if (!kh) {
            ulonglong2 p = red[r * 8 + cg];
            add2(a01, p.x);
            add2(a23, p.y);
            float s0, s1, s2, s3;
            unpack2(a01, s0, s1);
            unpack2(a23, s2, s3);
            float4 hv;
            hv.x = tanhf(s0 + xp.x);
            hv.y = tanhf(s1 + xp.y);
            hv.z = tanhf(s2 + xp.z);
            hv.w = tanhf(s3 + xp.w);
            *(float4*)&out[oidx] = hv;
            *(float4*)&g_h[t & 1][(size_t)(rowbase + r) * HH + c] = hv;
        }
        __syncthreads();

        // --- Publish: arrive on the rg counter (no return needed -> RED). ---
        if (tid == 0) {
            __threadfence();
            asm volatile("red.release.gpu.global.add.u32 [%0], %1;"
                         :: "l"(cnt), "r"(1u) : "memory");
        }
    }
}

// ---------------------------------------------------------------------------
// inputs: d_in[0]=inputs (B,T,I) f32, d_in[1]=h_prev (B,H) f32,
//         d_in[2]=W_xh (I,H) f32, d_in[3]=W_hh (H,H) f32, d_in[4]=b_h (H) f32
// out: (B,T,H) f32
// ---------------------------------------------------------------------------
extern "C" void kernel_launch(void* const* d_in, const int* in_sizes, int n_in,
                              void* d_out, int out_size) {
    const float* x      = (const float*)d_in[0];
    const float* h_prev = (const float*)d_in[1];
    const float* W_xh   = (const float*)d_in[2];
    const float* W_hh   = (const float*)d_in[3];
    const float* b_h    = (const float*)d_in[4];
    float* out = (float*)d_out;

    (void)in_sizes; (void)n_in; (void)out_size;

    // 128 KB (W) + 2 KB (red) = 133120 B dynamic smem -> 1 CTA/SM.
    const int smem_bytes = 1024 * CG_COLS * 4 + 2048;
    cudaFuncSetAttribute(rnn_recur, cudaFuncAttributeMaxDynamicSharedMemorySize,
                         smem_bytes);

    xproj_gemm<<<dim3(HH / 128, (BB * TT) / 128), 256>>>(x, W_xh, b_h, h_prev, out);
    rnn_recur<<<128, 256, smem_bytes>>>(W_hh, out);
}

// round 13
// speedup vs baseline: 2.7819x; 1.6972x over previous
#include <cuda_runtime.h>

#define BB 64
#define TT 512
#define II 512
#define HH 1024

// Recurrence tiling: 128 CTAs = 4 row-groups (16 rows) x 32 col-groups (32 cols).
#define RG_ROWS 16
#define CG_COLS 32
#define HS_STRIDE 1028          // padded h row stride (floats): rows-in-warp 2 apart
                                // -> bank shifts {0,8,16,24}, conflict-free; 16B-mult.
#define PB_STRIDE 44            // partial buffer row stride: shifts {0,24,16,8}; 16B-mult.

#define WS_FLOATS (1024 * CG_COLS)          // 32768
#define HS_FLOATS (RG_ROWS * HS_STRIDE)     // 16448
#define PB_FLOATS (4 * RG_ROWS * PB_STRIDE) // 2816

// h double buffer (ring) + per-row-group monotone barrier counters.
__device__ float g_h[2][BB * HH];
__device__ unsigned g_cnt[4 * 64];

// ---------------------------------------------------------------------------
// Packed f32x2 helpers (Blackwell FFMA2 — only reachable via PTX fma.rn.f32x2).
// ---------------------------------------------------------------------------
__device__ __forceinline__ unsigned long long pack2(float v) {
    unsigned long long r;
    asm("mov.b64 %0, {%1, %1};" : "=l"(r) : "f"(v));
    return r;
}
__device__ __forceinline__ void fma2(unsigned long long& d,
                                     unsigned long long a,
                                     unsigned long long b) {
    asm("fma.rn.f32x2 %0, %1, %2, %0;" : "+l"(d) : "l"(a), "l"(b));
}
__device__ __forceinline__ void unpack2(unsigned long long v, float& lo, float& hi) {
    asm("mov.b64 {%0, %1}, %2;" : "=f"(lo), "=f"(hi) : "l"(v));
}
__device__ __forceinline__ unsigned long long dl(double d) {
    return __double_as_longlong(d);
}

// ---------------------------------------------------------------------------
// Phase 1: x_proj = inputs(32768x512) @ W_xh(512x1024) + b  -> written to out.
// 128x128 tile, 8x8 microtile, BK=16, packed FFMA2 inner product.
// CTA (0,0) additionally resets the rg barrier counters and stages h_prev
// into ring[0] (stream order guarantees visibility to rnn_recur).
// ---------------------------------------------------------------------------
__global__ __launch_bounds__(256, 2) void xproj_gemm(
    const float* __restrict__ A, const float* __restrict__ W,
    const float* __restrict__ bias, const float* __restrict__ h_prev,
    float* __restrict__ C) {
    __shared__ __align__(16) float As[16][128];   // As[k][m]
    __shared__ __align__(16) float Bs[16][128];   // Bs[k][n]

    const int tid = threadIdx.x;

    // Merged init (one CTA): counters = 0, ring[0] = h_prev.
    if (blockIdx.x == 0 && blockIdx.y == 0) {
        if (tid < 4) g_cnt[tid * 64] = 0u;
        const float4* hp4 = (const float4*)h_prev;
        float4* r0 = (float4*)g_h[0];
#pragma unroll
        for (int i = 0; i < 64; i++)
            r0[tid + i * 256] = hp4[tid + i * 256];
    }

    const int m0 = blockIdx.y * 128;
    const int n0 = blockIdx.x * 128;
    const int tx = tid & 15;        // n microtile
    const int ty = tid >> 4;        // m microtile

    const int aRow = tid >> 2;
    const int aK   = (tid & 3) * 4;
    const int bRow = tid >> 5;
    const int bC   = (tid & 31) * 4;

    unsigned long long acc2[8][4];
#pragma unroll
    for (int i = 0; i < 8; i++)
#pragma unroll
        for (int j = 0; j < 4; j++) acc2[i][j] = 0ull;

    for (int k0 = 0; k0 < II; k0 += 16) {
#pragma unroll
        for (int it = 0; it < 2; it++) {
            int row = aRow + it * 64;
            float4 v = *(const float4*)&A[(size_t)(m0 + row) * II + k0 + aK];
            As[aK + 0][row] = v.x;
            As[aK + 1][row] = v.y;
            As[aK + 2][row] = v.z;
            As[aK + 3][row] = v.w;
        }
#pragma unroll
        for (int it = 0; it < 2; it++) {
            int rr = bRow + it * 8;
            *(float4*)&Bs[rr][bC] =
                *(const float4*)&W[(size_t)(k0 + rr) * HH + n0 + bC];
        }
        __syncthreads();
#pragma unroll
        for (int kk = 0; kk < 16; kk++) {
            float a[8];
            *(float4*)&a[0] = *(const float4*)&As[kk][ty * 8];
            *(float4*)&a[4] = *(const float4*)&As[kk][ty * 8 + 4];
            double2 bx = *(const double2*)&Bs[kk][tx * 8];
            double2 by = *(const double2*)&Bs[kk][tx * 8 + 4];
            unsigned long long b01 = dl(bx.x), b23 = dl(bx.y);
            unsigned long long b45 = dl(by.x), b67 = dl(by.y);
#pragma unroll
            for (int i = 0; i < 8; i++) {
                unsigned long long ap = pack2(a[i]);
                fma2(acc2[i][0], ap, b01);
                fma2(acc2[i][1], ap, b23);
                fma2(acc2[i][2], ap, b45);
                fma2(acc2[i][3], ap, b67);
            }
        }
        __syncthreads();
    }

#pragma unroll
    for (int i = 0; i < 8; i++) {
        int row = m0 + ty * 8 + i;
        float c[8];
#pragma unroll
        for (int j = 0; j < 4; j++) unpack2(acc2[i][j], c[2 * j], c[2 * j + 1]);
#pragma unroll
        for (int j = 0; j < 8; j++) c[j] += bias[n0 + tx * 8 + j];
        *(float4*)&C[(size_t)row * HH + n0 + tx * 8]     = *(float4*)&c[0];
        *(float4*)&C[(size_t)row * HH + n0 + tx * 8 + 4] = *(float4*)&c[4];
    }
}

// ---------------------------------------------------------------------------
// Phase 2: persistent recurrence. rg-scoped barrier (R12, cheap) + bulk
// coalesced h staging (R10, latency-tolerant) + 2x4x ks4 register blocking
// (new: 1 W-LDS feeds 4 FFMA2; LSU pressure halved, FMA-pipe becomes bound).
//
// CTA (rg, cgp): rows rg*16..+16, cols cgp*32..+32. SMEM: W tile 1024x32
// k-major (128 KB, resident all 512 steps), h tile 16x1028 (64.3 KB, staged
// per step), partial buffer 4x16x44 (11 KB). 203 KB -> 1 CTA/SM.
//
// Threads: tid = ks(2b)|rbl(3b)|cg(3b). Thread owns rows {rbl*2, rbl*2+1},
// cols cg*4..+4, k-range ks*256..+256. Per k: 1 W-LDS.128 (4 cols) + h from
// 2 float4-LDS per 4k; 4 FFMA2. Partials -> pbuf, 4-way ks reduce; every
// thread finishes 2 outputs (tanh + store to out and ring).
// ---------------------------------------------------------------------------
__global__ __launch_bounds__(256, 1) void rnn_recur(
    const float* __restrict__ Whh, float* __restrict__ out) {
    extern __shared__ __align__(16) float smem_dyn[];
    float* ws   = smem_dyn;              // [1024][32] k-major
    float* hs   = ws + WS_FLOATS;        // [16][1028]
    float* pbuf = hs + HS_FLOATS;        // [4][16][44]

    const int tid = threadIdx.x;
    const int cg  = tid & 7;
    const int rbl = (tid >> 3) & 7;
    const int ks  = tid >> 6;
    const int r0  = rbl * 2;

    const int rg      = blockIdx.x >> 5;
    const int rowbase = rg * RG_ROWS;
    const int colbase = (blockIdx.x & 31) * CG_COLS;
    unsigned* cnt     = &g_cnt[rg * 64];

    // --- Prologue: load W tile (1024 x 32) into smem k-major, once. ---
    {
        const float4* wsrc0 = (const float4*)(Whh + colbase);
        float4* wdst = (float4*)ws;
#pragma unroll
        for (int i = 0; i < 32; i++) {
            int idx4 = tid + i * 256;           // 8192 float4 total
            int k  = idx4 >> 3;                 // 8 float4 per W row
            int c4 = idx4 & 7;
            wdst[idx4] = wsrc0[(size_t)k * (HH / 4) + c4];
        }
    }
    __syncthreads();

    const float* hrow0 = hs + (size_t)r0 * HS_STRIDE + ks * 256;
    const float* wk0   = ws + (size_t)(ks * 256) * CG_COLS + cg * 4;

    // Epilogue mapping: thread finishes outputs idx = 2*tid, 2*tid+1.
    const int er = (2 * tid) >> 5;          // local row 0..15
    const int ec = (2 * tid) & 31;          // local col (even)

    for (int t = 1; t <= TT; t++) {
        // --- Wait: all 32 rg producers have published step t-1. ---
        if (t > 1) {
            if (tid == 0) {
                const unsigned want = 32u * (unsigned)(t - 1);
                unsigned v;
                do {
                    asm volatile("ld.acquire.gpu.global.b32 %0, [%1];"
                                 : "=r"(v) : "l"(cnt) : "memory");
                } while (v < want);
            }
            __syncthreads();
        }

        // --- Stage h tile (16 x 1024) into padded smem: coalesced, MLP=16. ---
        {
            const float4* src = (const float4*)(&g_h[(t - 1) & 1][rowbase * HH]);
            float4* dst = (float4*)hs;
#pragma unroll
            for (int i = 0; i < 16; i++) {
                int idx4 = tid + i * 256;       // 4096 float4 total
                int row  = idx4 >> 8;           // 256 float4 per h row
                int k4   = idx4 & 255;
                dst[row * (HS_STRIDE / 4) + k4] = __ldcg(&src[idx4]);
            }
        }

        // Prefetch x_proj operand for this thread's 2 outputs.
        const size_t oidx =
            ((size_t)(rowbase + er) * TT + (t - 1)) * HH + colbase + ec;
        float2 xp = *(const float2*)&out[oidx];
        __syncthreads();

        // --- Inner: 2 rows x 4 cols x 256 k, all operands from smem. ---
        unsigned long long a00 = 0ull, a01 = 0ull, a10 = 0ull, a11 = 0ull;
#pragma unroll 4
        for (int k = 0; k < 256; k += 4) {
            float4 hA = *(const float4*)(hrow0 + k);
            float4 hB = *(const float4*)(hrow0 + HS_STRIDE + k);
            const float* fA = &hA.x;
            const float* fB = &hB.x;
#pragma unroll
            for (int j = 0; j < 4; j++) {
                ulonglong2 w = *(const ulonglong2*)(wk0 + (size_t)(k + j) * CG_COLS);
                unsigned long long hp = pack2(fA[j]);
                fma2(a00, hp, w.x);
                fma2(a01, hp, w.y);
                hp = pack2(fB[j]);
                fma2(a10, hp, w.x);
                fma2(a11, hp, w.y);
            }
        }

        // --- Partials to smem: pbuf[ks][row][cg*4..+3]. ---
        {
            ulonglong2* p0 = (ulonglong2*)(pbuf +
                ((size_t)(ks * RG_ROWS + r0) * PB_STRIDE + cg * 4));
            ulonglong2* p1 = (ulonglong2*)(pbuf +
                ((size_t)(ks * RG_ROWS + r0 + 1) * PB_STRIDE + cg * 4));
            *p0 = make_ulonglong2(a00, a01);
            *p1 = make_ulonglong2(a10, a11);
        }
        __syncthreads();

        // --- ks-reduce + tanh + store: every thread finishes 2 outputs. ---
        {
            const float* pb = pbuf + (size_t)er * PB_STRIDE + ec;
            float2 s0 = *(const float2*)(pb + 0 * RG_ROWS * PB_STRIDE);
            float2 s1 = *(const float2*)(pb + 1 * RG_ROWS * PB_STRIDE);
            float2 s2 = *(const float2*)(pb + 2 * RG_ROWS * PB_STRIDE);
            float2 s3 = *(const float2*)(pb + 3 * RG_ROWS * PB_STRIDE);
            float2 hv;
            hv.x = tanhf(s0.x + s1.x + s2.x + s3.x + xp.x);
            hv.y = tanhf(s0.y + s1.y + s2.y + s3.y + xp.y);
            *(float2*)&out[oidx] = hv;
            *(float2*)&g_h[t & 1][(size_t)(rowbase + er) * HH + colbase + ec] = hv;
        }
        __syncthreads();

        // --- Publish: arrive on the rg counter (RED, no return). ---
        if (tid == 0) {
            __threadfence();
            asm volatile("red.release.gpu.global.add.u32 [%0], %1;"
                         :: "l"(cnt), "r"(1u) : "memory");
        }
    }
}

// ---------------------------------------------------------------------------
// inputs: d_in[0]=inputs (B,T,I) f32, d_in[1]=h_prev (B,H) f32,
//         d_in[2]=W_xh (I,H) f32, d_in[3]=W_hh (H,H) f32, d_in[4]=b_h (H) f32
// out: (B,T,H) f32
// ---------------------------------------------------------------------------
extern "C" void kernel_launch(void* const* d_in, const int* in_sizes, int n_in,
                              void* d_out, int out_size) {
    const float* x      = (const float*)d_in[0];
    const float* h_prev = (const float*)d_in[1];
    const float* W_xh   = (const float*)d_in[2];
    const float* W_hh   = (const float*)d_in[3];
    const float* b_h    = (const float*)d_in[4];
    float* out = (float*)d_out;

    (void)in_sizes; (void)n_in; (void)out_size;

    // 128 KB (W) + 64.3 KB (h) + 11 KB (partials) = 208128 B -> 1 CTA/SM.
    const int smem_bytes = (WS_FLOATS + HS_FLOATS + PB_FLOATS) * 4;
    cudaFuncSetAttribute(rnn_recur, cudaFuncAttributeMaxDynamicSharedMemorySize,
                         smem_bytes);

    xproj_gemm<<<dim3(HH / 128, (BB * TT) / 128), 256>>>(x, W_xh, b_h, h_prev, out);
    rnn_recur<<<128, 256, smem_bytes>>>(W_hh, out);
}